// round 1
// baseline (speedup 1.0000x reference)
#include <cuda_runtime.h>

// Problem constants (fixed by the dataset)
#define NN   50000
#define EE   800000
#define ETOT (NN + EE)      // edges + self loops
#define D1   128            // DIN and H*C1
#define HH   4
#define CC1  32
#define DOUT 32
#define SLOPE 0.2f

// ---------------- scratch (static device arrays: no allocation) -------------
__device__ int   g_deg[NN];
__device__ int   g_off[NN + 1];
__device__ int   g_cur[NN];
__device__ int   g_part[64];
__device__ int   g_ssrc[ETOT];
__device__ float g_xp1[NN * D1];
__device__ float g_h[NN * D1];
__device__ float g_xp2[NN * DOUT];
__device__ float g_as1[NN * HH];
__device__ float g_ad1[NN * HH];
__device__ float g_as2[NN];
__device__ float g_ad2[NN];

__device__ __forceinline__ float leaky(float v) { return v > 0.f ? v : SLOPE * v; }

// ---------------- CSR build -------------------------------------------------
__global__ void k_init() {
    int i = blockIdx.x * blockDim.x + threadIdx.x;
    if (i < NN) g_deg[i] = 1;   // self loop
}

__global__ void k_degree(const int* __restrict__ dst) {
    int e = blockIdx.x * blockDim.x + threadIdx.x;
    if (e < EE) atomicAdd(&g_deg[dst[e]], 1);
}

__global__ void k_scan1() {   // grid = ceil(NN/1024), block 1024
    __shared__ int s[1024];
    int t = threadIdx.x;
    int i = blockIdx.x * 1024 + t;
    int v = (i < NN) ? g_deg[i] : 0;
    s[t] = v;
    __syncthreads();
    #pragma unroll
    for (int d = 1; d < 1024; d <<= 1) {
        int x = (t >= d) ? s[t - d] : 0;
        __syncthreads();
        s[t] += x;
        __syncthreads();
    }
    if (i < NN) g_off[i] = s[t] - v;          // exclusive within chunk
    if (t == 1023) g_part[blockIdx.x] = s[1023];
}

__global__ void k_scan2() {
    if (threadIdx.x == 0 && blockIdx.x == 0) {
        int run = 0;
        int nchunks = (NN + 1023) / 1024;
        for (int c = 0; c < nchunks; c++) { int t = g_part[c]; g_part[c] = run; run += t; }
    }
}

__global__ void k_scan3() {
    int i = blockIdx.x * blockDim.x + threadIdx.x;
    if (i < NN) g_off[i] += g_part[i >> 10];
    if (i == 0) g_off[NN] = ETOT;
}

__global__ void k_self() {
    int i = blockIdx.x * blockDim.x + threadIdx.x;
    if (i < NN) { g_cur[i] = 1; g_ssrc[g_off[i]] = i; }
}

__global__ void k_scatter(const int* __restrict__ ei) {
    int e = blockIdx.x * blockDim.x + threadIdx.x;
    if (e < EE) {
        int s = ei[e];
        int d = ei[EE + e];
        int p = g_off[d] + atomicAdd(&g_cur[d], 1);
        g_ssrc[p] = s;
    }
}

// ---------------- GEMM1: xp1 = x @ W1  (50000x128 @ 128x128) ----------------
__global__ void k_gemm1(const float* __restrict__ x, const float* __restrict__ W) {
    __shared__ float Ws[32 * 128];   // [k][c] chunk
    __shared__ float Xs[32 * 32];    // [r][k] chunk
    int t = threadIdx.x;             // 256
    int row0 = blockIdx.x * 32;
    int c0 = (t & 31) * 4;
    int r0 = (t >> 5) * 4;
    float4 acc[4];
    acc[0] = make_float4(0, 0, 0, 0); acc[1] = acc[0]; acc[2] = acc[0]; acc[3] = acc[0];

    for (int kc = 0; kc < 128; kc += 32) {
        #pragma unroll
        for (int i = 0; i < 4; i++) {
            int idx = t + i * 256;   // 1024 float4 = 4096 floats
            ((float4*)Ws)[idx] = ((const float4*)(W + kc * 128))[idx];
        }
        {
            int r = t >> 3;
            int kk = (t & 7) * 4;
            int grow = row0 + r;
            float4 v = (grow < NN) ? *(const float4*)(x + grow * 128 + kc + kk)
                                   : make_float4(0, 0, 0, 0);
            *(float4*)(&Xs[r * 32 + kk]) = v;
        }
        __syncthreads();
        #pragma unroll
        for (int k = 0; k < 32; k++) {
            float4 b = *(const float4*)(&Ws[k * 128 + c0]);
            float a0 = Xs[(r0 + 0) * 32 + k];
            float a1 = Xs[(r0 + 1) * 32 + k];
            float a2 = Xs[(r0 + 2) * 32 + k];
            float a3 = Xs[(r0 + 3) * 32 + k];
            acc[0].x = fmaf(a0, b.x, acc[0].x); acc[0].y = fmaf(a0, b.y, acc[0].y);
            acc[0].z = fmaf(a0, b.z, acc[0].z); acc[0].w = fmaf(a0, b.w, acc[0].w);
            acc[1].x = fmaf(a1, b.x, acc[1].x); acc[1].y = fmaf(a1, b.y, acc[1].y);
            acc[1].z = fmaf(a1, b.z, acc[1].z); acc[1].w = fmaf(a1, b.w, acc[1].w);
            acc[2].x = fmaf(a2, b.x, acc[2].x); acc[2].y = fmaf(a2, b.y, acc[2].y);
            acc[2].z = fmaf(a2, b.z, acc[2].z); acc[2].w = fmaf(a2, b.w, acc[2].w);
            acc[3].x = fmaf(a3, b.x, acc[3].x); acc[3].y = fmaf(a3, b.y, acc[3].y);
            acc[3].z = fmaf(a3, b.z, acc[3].z); acc[3].w = fmaf(a3, b.w, acc[3].w);
        }
        __syncthreads();
    }
    #pragma unroll
    for (int r = 0; r < 4; r++) {
        int grow = row0 + r0 + r;
        if (grow < NN) *(float4*)(g_xp1 + grow * 128 + c0) = acc[r];
    }
}

// ---------------- attention dots, layer 1 -----------------------------------
__global__ void k_att1(const float* __restrict__ asrc, const float* __restrict__ adst) {
    int row = blockIdx.x;
    int t = threadIdx.x;                     // 128
    float v = g_xp1[row * 128 + t];
    float ps = v * asrc[t];
    float pd = v * adst[t];
    #pragma unroll
    for (int o = 16; o; o >>= 1) {
        ps += __shfl_xor_sync(0xffffffffu, ps, o);
        pd += __shfl_xor_sync(0xffffffffu, pd, o);
    }
    if ((t & 31) == 0) {
        int h = t >> 5;
        g_as1[row * 4 + h] = ps;
        g_ad1[row * 4 + h] = pd;
    }
}

// ---------------- layer-1 aggregation: warp per node ------------------------
__global__ void k_agg1(const float* __restrict__ b1) {
    int gw = (blockIdx.x * blockDim.x + threadIdx.x) >> 5;
    int lane = threadIdx.x & 31;
    if (gw >= NN) return;
    int i = gw;
    int s0 = g_off[i], s1 = g_off[i + 1];
    float4 ad4 = *(const float4*)(g_ad1 + i * 4);

    float m0 = -3e38f, m1 = -3e38f, m2 = -3e38f, m3 = -3e38f;
    for (int e = s0 + lane; e < s1; e += 32) {
        int src = g_ssrc[e];
        float4 a4 = *(const float4*)(g_as1 + src * 4);
        m0 = fmaxf(m0, leaky(a4.x + ad4.x));
        m1 = fmaxf(m1, leaky(a4.y + ad4.y));
        m2 = fmaxf(m2, leaky(a4.z + ad4.z));
        m3 = fmaxf(m3, leaky(a4.w + ad4.w));
    }
    #pragma unroll
    for (int o = 16; o; o >>= 1) {
        m0 = fmaxf(m0, __shfl_xor_sync(0xffffffffu, m0, o));
        m1 = fmaxf(m1, __shfl_xor_sync(0xffffffffu, m1, o));
        m2 = fmaxf(m2, __shfl_xor_sync(0xffffffffu, m2, o));
        m3 = fmaxf(m3, __shfl_xor_sync(0xffffffffu, m3, o));
    }
    int h = lane >> 3;
    float mh  = (h == 0) ? m0 : (h == 1) ? m1 : (h == 2) ? m2 : m3;
    float adh = (h == 0) ? ad4.x : (h == 1) ? ad4.y : (h == 2) ? ad4.z : ad4.w;

    float den = 0.f;
    float ax = 0.f, ay = 0.f, az = 0.f, aw = 0.f;
    for (int e = s0; e < s1; e++) {
        int src = g_ssrc[e];
        float lg = leaky(g_as1[src * 4 + h] + adh);
        float w = __expf(lg - mh);
        den += w;
        float4 v = *(const float4*)(g_xp1 + src * 128 + lane * 4);
        ax = fmaf(w, v.x, ax); ay = fmaf(w, v.y, ay);
        az = fmaf(w, v.z, az); aw = fmaf(w, v.w, aw);
    }
    float inv = 1.0f / den;
    float4 bb = *(const float4*)(b1 + lane * 4);
    float4 o;
    o.x = fmaxf(fmaf(ax, inv, bb.x), 0.f);
    o.y = fmaxf(fmaf(ay, inv, bb.y), 0.f);
    o.z = fmaxf(fmaf(az, inv, bb.z), 0.f);
    o.w = fmaxf(fmaf(aw, inv, bb.w), 0.f);
    *(float4*)(g_h + i * 128 + lane * 4) = o;
}

// ---------------- GEMM2: xp2 = h @ W2 (50000x128 @ 128x32) ------------------
__global__ void k_gemm2(const float* __restrict__ W2) {
    __shared__ float Ws[32 * 32];    // [k][c] chunk
    __shared__ float Xs[64 * 32];    // [r][k] chunk
    int t = threadIdx.x;             // 256
    int row0 = blockIdx.x * 64;
    int c = t & 31;
    int rb = (t >> 5) * 8;
    float acc[8] = {0, 0, 0, 0, 0, 0, 0, 0};

    for (int kc = 0; kc < 128; kc += 32) {
        ((float4*)Ws)[t] = ((const float4*)(W2 + kc * 32))[t];   // 1024 floats
        #pragma unroll
        for (int i = 0; i < 2; i++) {
            int idx = t + i * 256;           // 512 float4 = 2048 floats
            int r = idx >> 3;
            int kk = (idx & 7) * 4;
            int grow = row0 + r;
            float4 v = (grow < NN) ? *(const float4*)(g_h + grow * 128 + kc + kk)
                                   : make_float4(0, 0, 0, 0);
            *(float4*)(&Xs[r * 32 + kk]) = v;
        }
        __syncthreads();
        #pragma unroll
        for (int k = 0; k < 32; k++) {
            float b = Ws[k * 32 + c];
            #pragma unroll
            for (int j = 0; j < 8; j++)
                acc[j] = fmaf(Xs[(rb + j) * 32 + k], b, acc[j]);
        }
        __syncthreads();
    }
    #pragma unroll
    for (int j = 0; j < 8; j++) {
        int grow = row0 + rb + j;
        if (grow < NN) g_xp2[grow * 32 + c] = acc[j];
    }
}

// ---------------- attention dots, layer 2 -----------------------------------
__global__ void k_att2(const float* __restrict__ asrc, const float* __restrict__ adst) {
    int row = blockIdx.x * 8 + (threadIdx.x >> 5);
    int lane = threadIdx.x & 31;
    if (row >= NN) return;
    float v = g_xp2[row * 32 + lane];
    float ps = v * asrc[lane];
    float pd = v * adst[lane];
    #pragma unroll
    for (int o = 16; o; o >>= 1) {
        ps += __shfl_xor_sync(0xffffffffu, ps, o);
        pd += __shfl_xor_sync(0xffffffffu, pd, o);
    }
    if (lane == 0) { g_as2[row] = ps; g_ad2[row] = pd; }
}

// ---------------- layer-2 aggregation: warp per node ------------------------
__global__ void k_agg2(const float* __restrict__ b2, float* __restrict__ out) {
    int gw = (blockIdx.x * blockDim.x + threadIdx.x) >> 5;
    int lane = threadIdx.x & 31;
    if (gw >= NN) return;
    int i = gw;
    int s0 = g_off[i], s1 = g_off[i + 1];
    float ad = g_ad2[i];

    float m = -3e38f;
    for (int e = s0 + lane; e < s1; e += 32) {
        int src = g_ssrc[e];
        m = fmaxf(m, leaky(g_as2[src] + ad));
    }
    #pragma unroll
    for (int o = 16; o; o >>= 1)
        m = fmaxf(m, __shfl_xor_sync(0xffffffffu, m, o));

    float den = 0.f, acc = 0.f;
    for (int e = s0; e < s1; e++) {
        int src = g_ssrc[e];
        float lg = leaky(g_as2[src] + ad);
        float w = __expf(lg - m);
        den += w;
        acc = fmaf(w, g_xp2[src * 32 + lane], acc);
    }
    out[i * 32 + lane] = acc / den + b2[lane];
}

// ---------------- launch ----------------------------------------------------
extern "C" void kernel_launch(void* const* d_in, const int* in_sizes, int n_in,
                              void* d_out, int out_size) {
    const float* x     = (const float*)d_in[0];
    const int*   ei    = (const int*)  d_in[1];
    const float* W1    = (const float*)d_in[2];
    const float* as1   = (const float*)d_in[3];
    const float* ad1   = (const float*)d_in[4];
    const float* b1    = (const float*)d_in[5];
    const float* W2    = (const float*)d_in[6];
    const float* as2   = (const float*)d_in[7];
    const float* ad2   = (const float*)d_in[8];
    const float* b2    = (const float*)d_in[9];
    float* out = (float*)d_out;

    const int nblkN = (NN + 255) / 256;
    const int nblkE = (EE + 255) / 256;
    const int nchunks = (NN + 1023) / 1024;

    // CSR build
    k_init<<<nblkN, 256>>>();
    k_degree<<<nblkE, 256>>>(ei + EE);
    k_scan1<<<nchunks, 1024>>>();
    k_scan2<<<1, 32>>>();
    k_scan3<<<nblkN, 256>>>();
    k_self<<<nblkN, 256>>>();
    k_scatter<<<nblkE, 256>>>(ei);

    // layer 1
    k_gemm1<<<(NN + 31) / 32, 256>>>(x, W1);
    k_att1<<<NN, 128>>>(as1, ad1);
    k_agg1<<<(NN + 7) / 8, 256>>>(b1);

    // layer 2
    k_gemm2<<<(NN + 63) / 64, 256>>>(W2);
    k_att2<<<(NN + 7) / 8, 256>>>(as2, ad2);
    k_agg2<<<(NN + 7) / 8, 256>>>(b2, out);
}

// round 2
// speedup vs baseline: 1.2050x; 1.2050x over previous
#include <cuda_runtime.h>

// Problem constants (fixed by the dataset)
#define NN   50000
#define EE   800000
#define ETOT (NN + EE)      // edges + self loops
#define D1   128            // DIN and H*C1
#define HH   4
#define CC1  32
#define DOUT 32
#define SLOPE 0.2f

// ---------------- scratch (static device arrays: no allocation) -------------
__device__ int   g_deg[NN];
__device__ int   g_off[NN + 1];
__device__ int   g_cur[NN];
__device__ int   g_part[64];
__device__ int   g_ssrc[ETOT];
__device__ float g_xp1[NN * D1];
__device__ float g_h[NN * D1];
__device__ float g_xp2[NN * DOUT];
__device__ float g_as1[NN * HH];
__device__ float g_ad1[NN * HH];
__device__ float g_as2[NN];
__device__ float g_ad2[NN];

__device__ __forceinline__ float leaky(float v) { return v > 0.f ? v : SLOPE * v; }

// packed fp32x2 FMA (Blackwell): d = a*b + d on two lanes at once
__device__ __forceinline__ void fma2(unsigned long long& d, unsigned long long a,
                                     unsigned long long b) {
    asm("fma.rn.f32x2 %0, %1, %2, %0;" : "+l"(d) : "l"(a), "l"(b));
}
__device__ __forceinline__ unsigned long long pack2(float x) {
    unsigned long long r;
    asm("mov.b64 %0, {%1, %1};" : "=l"(r) : "f"(x));
    return r;
}
__device__ __forceinline__ float2 unpk2(unsigned long long v) {
    float2 r;
    asm("mov.b64 {%0, %1}, %2;" : "=f"(r.x), "=f"(r.y) : "l"(v));
    return r;
}

// ---------------- CSR build -------------------------------------------------
__global__ void k_init() {
    int i = blockIdx.x * blockDim.x + threadIdx.x;
    if (i < NN) g_deg[i] = 1;   // self loop
}

__global__ void k_degree(const int* __restrict__ dst) {
    int e4 = blockIdx.x * blockDim.x + threadIdx.x;
    if (e4 < EE / 4) {
        int4 d = ((const int4*)dst)[e4];
        atomicAdd(&g_deg[d.x], 1);
        atomicAdd(&g_deg[d.y], 1);
        atomicAdd(&g_deg[d.z], 1);
        atomicAdd(&g_deg[d.w], 1);
    }
}

__global__ void k_scan1() {   // grid = ceil(NN/1024), block 1024
    __shared__ int s[1024];
    int t = threadIdx.x;
    int i = blockIdx.x * 1024 + t;
    int v = (i < NN) ? g_deg[i] : 0;
    s[t] = v;
    __syncthreads();
    #pragma unroll
    for (int d = 1; d < 1024; d <<= 1) {
        int x = (t >= d) ? s[t - d] : 0;
        __syncthreads();
        s[t] += x;
        __syncthreads();
    }
    if (i < NN) g_off[i] = s[t] - v;          // exclusive within chunk
    if (t == 1023) g_part[blockIdx.x] = s[1023];
}

__global__ void k_scan2() {   // 1 block, 64 threads: scan the 49 chunk totals
    __shared__ int s[64];
    int t = threadIdx.x;
    const int nch = (NN + 1023) / 1024;
    int v = (t < nch) ? g_part[t] : 0;
    s[t] = v;
    __syncthreads();
    #pragma unroll
    for (int d = 1; d < 64; d <<= 1) {
        int x = (t >= d) ? s[t - d] : 0;
        __syncthreads();
        s[t] += x;
        __syncthreads();
    }
    if (t < nch) g_part[t] = s[t] - v;        // exclusive chunk bases
}

__global__ void k_scan3self() {
    int i = blockIdx.x * blockDim.x + threadIdx.x;
    if (i < NN) {
        int o = g_off[i] + g_part[i >> 10];
        g_off[i] = o;
        g_cur[i] = 1;        // slot 0 of each segment = self loop
        g_ssrc[o] = i;
    }
    if (i == 0) g_off[NN] = ETOT;
}

__global__ void k_scatter(const int* __restrict__ ei) {
    int e4 = blockIdx.x * blockDim.x + threadIdx.x;
    if (e4 < EE / 4) {
        int4 s = ((const int4*)ei)[e4];
        int4 d = ((const int4*)(ei + EE))[e4];
        int p;
        p = g_off[d.x] + atomicAdd(&g_cur[d.x], 1); g_ssrc[p] = s.x;
        p = g_off[d.y] + atomicAdd(&g_cur[d.y], 1); g_ssrc[p] = s.y;
        p = g_off[d.z] + atomicAdd(&g_cur[d.z], 1); g_ssrc[p] = s.z;
        p = g_off[d.w] + atomicAdd(&g_cur[d.w], 1); g_ssrc[p] = s.w;
    }
}

// ---- GEMM1: xp1 = x @ W1 (50000x128 @ 128x128) + fused attention dots ------
// block: 64 rows x 128 cols, 256 threads; warp = 8 rows (uniform) x 128 cols;
// thread = 8 rows x 4 cols, accumulated as fp32x2 pairs.
__global__ void __launch_bounds__(256)
k_gemm1(const float* __restrict__ x, const float* __restrict__ W,
        const float* __restrict__ asrc, const float* __restrict__ adst) {
    __shared__ float Ws[32][128];   // k-major
    __shared__ float Xs[32][64];    // k-major (transposed on load)
    int t = threadIdx.x;
    int lane = t & 31;
    int warp = t >> 5;
    int row0 = blockIdx.x * 64;
    int c0 = lane * 4;
    int r0 = warp * 8;

    unsigned long long acc[8][2];
    #pragma unroll
    for (int r = 0; r < 8; r++) { acc[r][0] = 0ull; acc[r][1] = 0ull; }

    for (int kc = 0; kc < 128; kc += 32) {
        #pragma unroll
        for (int i = 0; i < 4; i++) {
            int idx = t + i * 256;
            ((float4*)&Ws[0][0])[idx] = ((const float4*)(W + kc * 128))[idx];
        }
        #pragma unroll
        for (int i = 0; i < 2; i++) {
            int id = t + i * 256;          // 512 float4 = 64 rows x 32 k
            int row = id >> 3;
            int k4 = (id & 7) * 4;
            int grow = row0 + row;
            float4 v = (grow < NN) ? *(const float4*)(x + grow * 128 + kc + k4)
                                   : make_float4(0, 0, 0, 0);
            Xs[k4 + 0][row] = v.x; Xs[k4 + 1][row] = v.y;
            Xs[k4 + 2][row] = v.z; Xs[k4 + 3][row] = v.w;
        }
        __syncthreads();
        #pragma unroll 8
        for (int k = 0; k < 32; k++) {
            float4 alo = *(const float4*)&Xs[k][r0];       // warp-uniform rows
            float4 ahi = *(const float4*)&Xs[k][r0 + 4];
            ulonglong2 b = *(const ulonglong2*)&Ws[k][c0];
            unsigned long long ap;
            ap = pack2(alo.x); fma2(acc[0][0], ap, b.x); fma2(acc[0][1], ap, b.y);
            ap = pack2(alo.y); fma2(acc[1][0], ap, b.x); fma2(acc[1][1], ap, b.y);
            ap = pack2(alo.z); fma2(acc[2][0], ap, b.x); fma2(acc[2][1], ap, b.y);
            ap = pack2(alo.w); fma2(acc[3][0], ap, b.x); fma2(acc[3][1], ap, b.y);
            ap = pack2(ahi.x); fma2(acc[4][0], ap, b.x); fma2(acc[4][1], ap, b.y);
            ap = pack2(ahi.y); fma2(acc[5][0], ap, b.x); fma2(acc[5][1], ap, b.y);
            ap = pack2(ahi.z); fma2(acc[6][0], ap, b.x); fma2(acc[6][1], ap, b.y);
            ap = pack2(ahi.w); fma2(acc[7][0], ap, b.x); fma2(acc[7][1], ap, b.y);
        }
        __syncthreads();
    }

    // epilogue: store xp1 + fused per-head attention dots
    float4 asv = *(const float4*)(asrc + c0);
    float4 adv = *(const float4*)(adst + c0);
    int h = lane >> 3;
    #pragma unroll
    for (int r = 0; r < 8; r++) {
        float2 lo = unpk2(acc[r][0]);
        float2 hi = unpk2(acc[r][1]);
        int grow = row0 + r0 + r;
        if (grow < NN)
            *(float4*)(g_xp1 + grow * 128 + c0) = make_float4(lo.x, lo.y, hi.x, hi.y);
        float ps = lo.x * asv.x + lo.y * asv.y + hi.x * asv.z + hi.y * asv.w;
        float pd = lo.x * adv.x + lo.y * adv.y + hi.x * adv.z + hi.y * adv.w;
        #pragma unroll
        for (int o = 1; o < 8; o <<= 1) {
            ps += __shfl_xor_sync(0xffffffffu, ps, o);
            pd += __shfl_xor_sync(0xffffffffu, pd, o);
        }
        if ((lane & 7) == 0 && grow < NN) {
            g_as1[grow * 4 + h] = ps;
            g_ad1[grow * 4 + h] = pd;
        }
    }
}

// ---- layer-1 aggregation: warp per node, chunked softmax (no max pass) -----
__global__ void __launch_bounds__(256) k_agg1(const float* __restrict__ b1) {
    int gw = (blockIdx.x * blockDim.x + threadIdx.x) >> 5;
    int lane = threadIdx.x & 31;
    if (gw >= NN) return;
    int i = gw;
    int s0 = g_off[i], s1 = g_off[i + 1];
    int h = lane >> 3;
    int es = lane & 7;
    float adh = g_ad1[i * 4 + h];

    float den = 0.f;
    float ax = 0.f, ay = 0.f, az = 0.f, aw = 0.f;
    for (int base = s0; base < s1; base += 8) {
        int e = base + es;
        int src_l = 0;
        float w_l = 0.f;
        if (e < s1) {
            src_l = g_ssrc[e];
            w_l = __expf(leaky(g_as1[src_l * 4 + h] + adh));
        }
        den += w_l;
        int n = min(8, s1 - base);
        for (int j = 0; j < n; j++) {
            int sl = (h << 3) | j;
            int src = __shfl_sync(0xffffffffu, src_l, sl);
            float w  = __shfl_sync(0xffffffffu, w_l, sl);
            float4 v = *(const float4*)(g_xp1 + src * 128 + lane * 4);
            ax = fmaf(w, v.x, ax); ay = fmaf(w, v.y, ay);
            az = fmaf(w, v.z, az); aw = fmaf(w, v.w, aw);
        }
    }
    den += __shfl_xor_sync(0xffffffffu, den, 1);
    den += __shfl_xor_sync(0xffffffffu, den, 2);
    den += __shfl_xor_sync(0xffffffffu, den, 4);
    float inv = 1.0f / den;
    float4 bb = *(const float4*)(b1 + lane * 4);
    float4 o;
    o.x = fmaxf(fmaf(ax, inv, bb.x), 0.f);
    o.y = fmaxf(fmaf(ay, inv, bb.y), 0.f);
    o.z = fmaxf(fmaf(az, inv, bb.z), 0.f);
    o.w = fmaxf(fmaf(aw, inv, bb.w), 0.f);
    *(float4*)(g_h + i * 128 + lane * 4) = o;
}

// ---- GEMM2: xp2 = h @ W2 (50000x128 @ 128x32) + fused attention dots -------
// block: 128 rows x 32 cols, 256 threads; thread = 8 rows x 2 cols (1 pair)
__global__ void __launch_bounds__(256)
k_gemm2(const float* __restrict__ W2,
        const float* __restrict__ asrc, const float* __restrict__ adst) {
    __shared__ float Ws[32][32];    // k-major
    __shared__ float Xs[32][128];   // k-major
    int t = threadIdx.x;
    int lane = t & 31;
    int row0 = blockIdx.x * 128;
    int c0 = (t & 15) * 2;
    int r0 = (t >> 4) * 8;

    unsigned long long acc[8];
    #pragma unroll
    for (int r = 0; r < 8; r++) acc[r] = 0ull;

    for (int kc = 0; kc < 128; kc += 32) {
        ((float4*)&Ws[0][0])[t] = ((const float4*)(W2 + kc * 32))[t];
        #pragma unroll
        for (int i = 0; i < 4; i++) {
            int id = t + i * 256;          // 1024 float4 = 128 rows x 32 k
            int row = id >> 3;
            int k4 = (id & 7) * 4;
            int grow = row0 + row;
            float4 v = (grow < NN) ? *(const float4*)(g_h + grow * 128 + kc + k4)
                                   : make_float4(0, 0, 0, 0);
            Xs[k4 + 0][row] = v.x; Xs[k4 + 1][row] = v.y;
            Xs[k4 + 2][row] = v.z; Xs[k4 + 3][row] = v.w;
        }
        __syncthreads();
        #pragma unroll 8
        for (int k = 0; k < 32; k++) {
            float4 alo = *(const float4*)&Xs[k][r0];
            float4 ahi = *(const float4*)&Xs[k][r0 + 4];
            unsigned long long b = *(const unsigned long long*)&Ws[k][c0];
            unsigned long long ap;
            ap = pack2(alo.x); fma2(acc[0], ap, b);
            ap = pack2(alo.y); fma2(acc[1], ap, b);
            ap = pack2(alo.z); fma2(acc[2], ap, b);
            ap = pack2(alo.w); fma2(acc[3], ap, b);
            ap = pack2(ahi.x); fma2(acc[4], ap, b);
            ap = pack2(ahi.y); fma2(acc[5], ap, b);
            ap = pack2(ahi.z); fma2(acc[6], ap, b);
            ap = pack2(ahi.w); fma2(acc[7], ap, b);
        }
        __syncthreads();
    }

    float2 asv = *(const float2*)(asrc + c0);
    float2 adv = *(const float2*)(adst + c0);
    #pragma unroll
    for (int r = 0; r < 8; r++) {
        float2 v = unpk2(acc[r]);
        int grow = row0 + r0 + r;
        if (grow < NN)
            *(float2*)(g_xp2 + grow * 32 + c0) = v;
        float ps = v.x * asv.x + v.y * asv.y;
        float pd = v.x * adv.x + v.y * adv.y;
        #pragma unroll
        for (int o = 1; o < 16; o <<= 1) {
            ps += __shfl_xor_sync(0xffffffffu, ps, o);
            pd += __shfl_xor_sync(0xffffffffu, pd, o);
        }
        if ((lane & 15) == 0 && grow < NN) {
            g_as2[grow] = ps;
            g_ad2[grow] = pd;
        }
    }
}

// ---- layer-2 aggregation: warp per node, chunked softmax (no max pass) -----
__global__ void __launch_bounds__(256)
k_agg2(const float* __restrict__ b2, float* __restrict__ out) {
    int gw = (blockIdx.x * blockDim.x + threadIdx.x) >> 5;
    int lane = threadIdx.x & 31;
    if (gw >= NN) return;
    int i = gw;
    int s0 = g_off[i], s1 = g_off[i + 1];
    float ad = g_ad2[i];

    float den = 0.f, acc = 0.f;
    for (int base = s0; base < s1; base += 32) {
        int e = base + lane;
        int src_l = 0;
        float w_l = 0.f;
        if (e < s1) {
            src_l = g_ssrc[e];
            w_l = __expf(leaky(g_as2[src_l] + ad));
        }
        den += w_l;
        int n = min(32, s1 - base);
        for (int j = 0; j < n; j++) {
            int src = __shfl_sync(0xffffffffu, src_l, j);
            float w  = __shfl_sync(0xffffffffu, w_l, j);
            acc = fmaf(w, g_xp2[src * 32 + lane], acc);
        }
    }
    #pragma unroll
    for (int o = 16; o; o >>= 1)
        den += __shfl_xor_sync(0xffffffffu, den, o);
    out[i * 32 + lane] = acc / den + b2[lane];
}

// ---------------- launch ----------------------------------------------------
extern "C" void kernel_launch(void* const* d_in, const int* in_sizes, int n_in,
                              void* d_out, int out_size) {
    const float* x   = (const float*)d_in[0];
    const int*   ei  = (const int*)  d_in[1];
    const float* W1  = (const float*)d_in[2];
    const float* as1 = (const float*)d_in[3];
    const float* ad1 = (const float*)d_in[4];
    const float* b1  = (const float*)d_in[5];
    const float* W2  = (const float*)d_in[6];
    const float* as2 = (const float*)d_in[7];
    const float* ad2 = (const float*)d_in[8];
    const float* b2  = (const float*)d_in[9];
    float* out = (float*)d_out;

    const int nblkN = (NN + 255) / 256;
    const int nchunks = (NN + 1023) / 1024;
    const int nblkE4 = (EE / 4 + 255) / 256;
    const int nblkW = (NN * 32 + 255) / 256;   // one warp per node

    // CSR build
    k_init<<<nblkN, 256>>>();
    k_degree<<<nblkE4, 256>>>(ei + EE);
    k_scan1<<<nchunks, 1024>>>();
    k_scan2<<<1, 64>>>();
    k_scan3self<<<nblkN, 256>>>();
    k_scatter<<<nblkE4, 256>>>(ei);

    // layer 1
    k_gemm1<<<(NN + 63) / 64, 256>>>(x, W1, as1, ad1);
    k_agg1<<<nblkW, 256>>>(b1);

    // layer 2
    k_gemm2<<<(NN + 127) / 128, 256>>>(W2, as2, ad2);
    k_agg2<<<nblkW, 256>>>(b2, out);
}